// round 1
// baseline (speedup 1.0000x reference)
#include <cuda_runtime.h>

// Problem constants
#define N_NODES 400
#define NM1     399          // N_NODES - 1
#define E_EDGES (N_NODES * NM1)   // 159600
#define BATCH   32

// Each thread handles TWO consecutive edges for one batch element and writes
// a single float4 (two [1-t, t] one-hot pairs). Output layout: [B, E, 2] fp32,
// contiguous, so float4 index = b * (E/2) + pair.
__global__ void nri_edge_onehot_kernel(const float* __restrict__ adj,
                                       float4* __restrict__ out) {
    const int pair = blockIdx.x * blockDim.x + threadIdx.x;   // 0 .. E/2-1
    const int b    = blockIdx.y;                              // 0 .. BATCH-1
    if (pair >= E_EDGES / 2) return;

    const int e0 = pair * 2;
    const int e1 = e0 + 1;

    // Recover (send, rec) from row-major off-diagonal enumeration:
    // send = e / 399 ; k = e % 399 ; rec = k + (k >= send)
    const int s0 = e0 / NM1;
    const int k0 = e0 - s0 * NM1;
    const int r0 = k0 + (k0 >= s0 ? 1 : 0);

    const int s1 = e1 / NM1;
    const int k1 = e1 - s1 * NM1;
    const int r1 = k1 + (k1 >= s1 ? 1 : 0);

    const float a0 = __ldg(&adj[s0 * N_NODES + r0]);
    const float a1 = __ldg(&adj[s1 * N_NODES + r1]);

    const float t0 = (a0 != 0.0f) ? 1.0f : 0.0f;
    const float t1 = (a1 != 0.0f) ? 1.0f : 0.0f;

    out[(size_t)b * (E_EDGES / 2) + pair] =
        make_float4(1.0f - t0, t0, 1.0f - t1, t1);
}

extern "C" void kernel_launch(void* const* d_in, const int* in_sizes, int n_in,
                              void* d_out, int out_size) {
    // Input order per reference setup_inputs():
    //   0: inputs  [32,400,12,1]   (unused)
    //   1: weather [32,12,4]       (unused)
    //   2: rel_rec [E,400]         (unused — indices recovered arithmetically)
    //   3: rel_send[E,400]         (unused)
    //   4: adj_matrix [400,400]    fp32
    const float* adj = (const float*)d_in[4];
    float4* out = (float4*)d_out;

    const int pairs = E_EDGES / 2;            // 79800 per batch
    const int threads = 256;
    dim3 grid((pairs + threads - 1) / threads, BATCH);
    nri_edge_onehot_kernel<<<grid, threads>>>(adj, out);
}

// round 2
// speedup vs baseline: 1.0239x; 1.0239x over previous
#include <cuda_runtime.h>

// Problem constants
#define N_NODES 400
#define NM1     399                  // N_NODES - 1
#define E_EDGES (N_NODES * NM1)      // 159600
#define PAIRS   (E_EDGES / 2)        // 79800 float4 elements per batch
#define BATCH   32
#define BPT     8                    // batches stored per thread
#define BGROUPS (BATCH / BPT)        // grid.y = 4

// The [E,2] one-hot is identical across all 32 batch slots. Each thread
// computes ONE float4 (two edges) and broadcasts it to BPT batch slots with
// independent STG.128s. grid.y covers the remaining batch groups so the grid
// stays large enough (1248 blocks) for clean SM load balance.
__global__ void nri_edge_onehot_bcast_kernel(const float* __restrict__ adj,
                                             float4* __restrict__ out) {
    const int pair = blockIdx.x * blockDim.x + threadIdx.x;   // 0 .. PAIRS-1
    if (pair >= PAIRS) return;

    const int e0 = pair * 2;
    const int e1 = e0 + 1;

    // Recover (send, rec) from row-major off-diagonal enumeration:
    // send = e / 399 ; k = e % 399 ; rec = k + (k >= send)
    const int s0 = e0 / NM1;
    const int k0 = e0 - s0 * NM1;
    const int r0 = k0 + (k0 >= s0 ? 1 : 0);

    const int s1 = e1 / NM1;
    const int k1 = e1 - s1 * NM1;
    const int r1 = k1 + (k1 >= s1 ? 1 : 0);

    const float a0 = __ldg(&adj[s0 * N_NODES + r0]);
    const float a1 = __ldg(&adj[s1 * N_NODES + r1]);

    const float t0 = (a0 != 0.0f) ? 1.0f : 0.0f;
    const float t1 = (a1 != 0.0f) ? 1.0f : 0.0f;
    const float4 v = make_float4(1.0f - t0, t0, 1.0f - t1, t1);

    // Broadcast to BPT batch slots (independent, fire-and-forget stores).
    const size_t base = (size_t)(blockIdx.y * BPT) * PAIRS + pair;
    #pragma unroll
    for (int i = 0; i < BPT; i++) {
        out[base + (size_t)i * PAIRS] = v;
    }
}

extern "C" void kernel_launch(void* const* d_in, const int* in_sizes, int n_in,
                              void* d_out, int out_size) {
    // Input order per reference setup_inputs():
    //   0: inputs  [32,400,12,1]   (unused)
    //   1: weather [32,12,4]       (unused)
    //   2: rel_rec [E,400]         (unused — indices recovered arithmetically)
    //   3: rel_send[E,400]         (unused)
    //   4: adj_matrix [400,400]    fp32
    const float* adj = (const float*)d_in[4];
    float4* out = (float4*)d_out;

    const int threads = 256;
    dim3 grid((PAIRS + threads - 1) / threads, BGROUPS);  // (312, 4)
    nri_edge_onehot_bcast_kernel<<<grid, threads>>>(adj, out);
}